// round 4
// baseline (speedup 1.0000x reference)
#include <cuda_runtime.h>

#define N_NODES 100000
#define N_EDGES 1600000
#define IN_DIM  128
#define HID     64
#define N_GRAPHS 64

// ---------------- static device scratch (no allocations allowed) ----------------
__device__ int   g_cnt[N_NODES];          // in-degree (excluding self-loop)
__device__ int   g_cur[N_NODES];          // scatter cursors
__device__ int   g_off[N_NODES + 1];      // CSR offsets by dst
__device__ float g_dis[N_NODES];          // deg^{-1/2}
__device__ int   g_csr_src[N_EDGES];
__device__ float g_csr_norm[N_EDGES];
__device__ __align__(16) float g_A[(size_t)N_NODES * HID];  // GEMM output (msg source)
__device__ __align__(16) float g_B[(size_t)N_NODES * HID];  // layer output
__device__ float g_pooled[N_GRAPHS * HID];

// ---------------- preprocessing ----------------
__global__ __launch_bounds__(256) void k_zero() {
    int i = blockIdx.x * blockDim.x + threadIdx.x;
    if (i < N_NODES) { g_cnt[i] = 0; g_cur[i] = 0; }
}

__global__ __launch_bounds__(256) void k_count(const int* __restrict__ dst32) {
    int e = blockIdx.x * blockDim.x + threadIdx.x;
    if (e < N_EDGES) atomicAdd(&g_cnt[dst32[e]], 1);
}

__global__ __launch_bounds__(256) void k_dis() {
    int i = blockIdx.x * blockDim.x + threadIdx.x;
    if (i < N_NODES) g_dis[i] = rsqrtf((float)(g_cnt[i] + 1));  // +1 self-loop
}

// single-block exclusive scan over g_cnt -> g_off (100k elements)
#define SCAN_T 1024
__global__ __launch_bounds__(SCAN_T) void k_scan() {
    __shared__ int part[SCAN_T];
    const int chunk = (N_NODES + SCAN_T - 1) / SCAN_T;  // 98
    int t = threadIdx.x;
    int base = t * chunk;
    int s = 0;
    for (int i = 0; i < chunk; i++) {
        int idx = base + i;
        if (idx < N_NODES) s += g_cnt[idx];
    }
    part[t] = s;
    __syncthreads();
    // inclusive Hillis-Steele scan on partials
    for (int d = 1; d < SCAN_T; d <<= 1) {
        int v = (t >= d) ? part[t - d] : 0;
        __syncthreads();
        part[t] += v;
        __syncthreads();
    }
    int run = (t == 0) ? 0 : part[t - 1];
    for (int i = 0; i < chunk; i++) {
        int idx = base + i;
        if (idx < N_NODES) {
            g_off[idx] = run;
            run += g_cnt[idx];
        }
    }
    if (t == SCAN_T - 1) g_off[N_NODES] = N_EDGES;
}

__global__ __launch_bounds__(256) void k_scatter(const int* __restrict__ ei) {
    int e = blockIdx.x * blockDim.x + threadIdx.x;
    if (e >= N_EDGES) return;
    int s = ei[e];
    int d = ei[N_EDGES + e];
    int pos = g_off[d] + atomicAdd(&g_cur[d], 1);
    g_csr_src[pos] = s;
    g_csr_norm[pos] = g_dis[s] * g_dis[d];
}

// ---------------- GEMM: A = act(X) @ W  (X external or g_B) ----------------
#define GEMM_T 128
template<int K, bool RELU, bool FROM_B>
__global__ __launch_bounds__(GEMM_T) void k_gemm(const float* __restrict__ Xext,
                                                 const float* __restrict__ W) {
    __shared__ float Wsh[K * HID];
    for (int i = threadIdx.x; i < K * HID; i += blockDim.x) Wsh[i] = W[i];
    __syncthreads();

    int row = blockIdx.x * blockDim.x + threadIdx.x;
    if (row >= N_NODES) return;

    const float* X = FROM_B ? g_B : Xext;
    const float4* xr = (const float4*)(X + (size_t)row * K);

    float acc[HID];
#pragma unroll
    for (int c = 0; c < HID; c++) acc[c] = 0.0f;

#pragma unroll 2
    for (int k4 = 0; k4 < K / 4; k4++) {
        float4 xv = xr[k4];
        if (RELU) {
            xv.x = fmaxf(xv.x, 0.0f); xv.y = fmaxf(xv.y, 0.0f);
            xv.z = fmaxf(xv.z, 0.0f); xv.w = fmaxf(xv.w, 0.0f);
        }
        float xk_arr[4] = {xv.x, xv.y, xv.z, xv.w};
#pragma unroll
        for (int kk = 0; kk < 4; kk++) {
            float xk = xk_arr[kk];
            const float4* wr = (const float4*)(Wsh + (k4 * 4 + kk) * HID);
#pragma unroll
            for (int c4 = 0; c4 < 16; c4++) {
                float4 w = wr[c4];
                acc[4 * c4 + 0] += xk * w.x;
                acc[4 * c4 + 1] += xk * w.y;
                acc[4 * c4 + 2] += xk * w.z;
                acc[4 * c4 + 3] += xk * w.w;
            }
        }
    }

    float4* o = (float4*)(g_A + (size_t)row * HID);
#pragma unroll
    for (int c4 = 0; c4 < 16; c4++)
        o[c4] = make_float4(acc[4 * c4], acc[4 * c4 + 1], acc[4 * c4 + 2], acc[4 * c4 + 3]);
}

// ---------------- aggregation: one warp per dst node ----------------
// B[d,:] = A[d,:]*dis[d]^2 + b + sum_{e in CSR[d]} A[src_e,:]*norm_e
__global__ __launch_bounds__(256) void k_agg(const float* __restrict__ bias) {
    int w = (blockIdx.x * blockDim.x + threadIdx.x) >> 5;
    if (w >= N_NODES) return;
    int lane = threadIdx.x & 31;

    const float2* A2 = (const float2*)g_A;
    float dis = g_dis[w];
    float2 b2 = ((const float2*)bias)[lane];
    float2 self = A2[(size_t)w * 32 + lane];
    float sn = dis * dis;
    float ax = self.x * sn + b2.x;
    float ay = self.y * sn + b2.y;

    int p   = g_off[w];
    int end = g_off[w + 1];
    // 2-edge unroll for MLP on the L2 gathers
    for (; p + 2 <= end; p += 2) {
        int   s0 = g_csr_src[p];
        float n0 = g_csr_norm[p];
        int   s1 = g_csr_src[p + 1];
        float n1 = g_csr_norm[p + 1];
        float2 v0 = A2[(size_t)s0 * 32 + lane];
        float2 v1 = A2[(size_t)s1 * 32 + lane];
        ax += v0.x * n0; ay += v0.y * n0;
        ax += v1.x * n1; ay += v1.y * n1;
    }
    if (p < end) {
        int   s0 = g_csr_src[p];
        float n0 = g_csr_norm[p];
        float2 v0 = A2[(size_t)s0 * 32 + lane];
        ax += v0.x * n0; ay += v0.y * n0;
    }

    ((float2*)g_B)[(size_t)w * 32 + lane] = make_float2(ax, ay);
}

// ---------------- global mean pool (batch is sorted int32) ----------------
__device__ __forceinline__ int lb_i32(const int* a, int n, int v) {
    int lo = 0, hi = n;
    while (lo < hi) {
        int mid = (lo + hi) >> 1;
        if (a[mid] < v) lo = mid + 1; else hi = mid;
    }
    return lo;
}

__global__ __launch_bounds__(256) void k_pool(const int* __restrict__ batch) {
    int g = blockIdx.x;                 // one block per graph
    int lo = lb_i32(batch, N_NODES, g);
    int hi = lb_i32(batch, N_NODES, g + 1);
    int c = threadIdx.x & 63;
    int sub = threadIdx.x >> 6;         // 0..3
    float s = 0.0f;
    for (int i = lo + sub; i < hi; i += 4)
        s += g_B[(size_t)i * HID + c];
    __shared__ float red[256];
    red[threadIdx.x] = s;
    __syncthreads();
    if (sub == 0) {
        float tot = red[c] + red[64 + c] + red[128 + c] + red[192 + c];
        float cnt = (float)(hi - lo);
        g_pooled[g * HID + c] = tot / fmaxf(cnt, 1.0f);
    }
}

// ---------------- classifier MLP: [64,64] -> relu[64,32] -> [64,2] ----------------
__global__ __launch_bounds__(64) void k_cls(const float* __restrict__ Wc1,
                                            const float* __restrict__ bc1,
                                            const float* __restrict__ Wc2,
                                            const float* __restrict__ bc2,
                                            float* __restrict__ out) {
    __shared__ float W1s[64 * 32];
    __shared__ float W2s[32 * 2];
    int t = threadIdx.x;  // 64 threads, one per graph
    for (int i = t; i < 64 * 32; i += 64) W1s[i] = Wc1[i];
    if (t < 64) W2s[t] = Wc2[t];
    __syncthreads();

    float p[64];
#pragma unroll
    for (int k = 0; k < 64; k++) p[k] = g_pooled[t * 64 + k];

    float h[32];
#pragma unroll
    for (int j = 0; j < 32; j++) {
        float s = bc1[j];
#pragma unroll
        for (int k = 0; k < 64; k++) s += p[k] * W1s[k * 32 + j];
        h[j] = fmaxf(s, 0.0f);
    }
#pragma unroll
    for (int o = 0; o < 2; o++) {
        float s = bc2[o];
#pragma unroll
        for (int j = 0; j < 32; j++) s += h[j] * W2s[j * 2 + o];
        out[t * 2 + o] = s;
    }
}

// ---------------- launch ----------------
extern "C" void kernel_launch(void* const* d_in, const int* in_sizes, int n_in,
                              void* d_out, int out_size) {
    const float* x     = (const float*)d_in[0];
    const int*   ei    = (const int*)d_in[1];    // int32 (JAX x64 disabled)
    const int*   batch = (const int*)d_in[2];    // int32
    const float* W1  = (const float*)d_in[3];
    const float* b1  = (const float*)d_in[4];
    const float* W2  = (const float*)d_in[5];
    const float* b2  = (const float*)d_in[6];
    const float* W3  = (const float*)d_in[7];
    const float* b3  = (const float*)d_in[8];
    const float* Wc1 = (const float*)d_in[9];
    const float* bc1 = (const float*)d_in[10];
    const float* Wc2 = (const float*)d_in[11];
    const float* bc2 = (const float*)d_in[12];
    float* out = (float*)d_out;

    const int TB = 256;
    const int gN  = (N_NODES + TB - 1) / TB;
    const int gE  = (N_EDGES + TB - 1) / TB;
    const int gW  = (N_NODES * 32 + TB - 1) / TB;        // warp-per-node grid
    const int gG  = (N_NODES + GEMM_T - 1) / GEMM_T;     // gemm grid (128 thr)

    // CSR-by-dst preprocessing
    k_zero<<<gN, TB>>>();
    k_count<<<gE, TB>>>(ei + N_EDGES);
    k_dis<<<gN, TB>>>();
    k_scan<<<1, SCAN_T>>>();
    k_scatter<<<gE, TB>>>(ei);

    // layer 1
    k_gemm<IN_DIM, false, false><<<gG, GEMM_T>>>(x, W1);
    k_agg<<<gW, TB>>>(b1);
    // layer 2
    k_gemm<HID, true, true><<<gG, GEMM_T>>>(nullptr, W2);
    k_agg<<<gW, TB>>>(b2);
    // layer 3
    k_gemm<HID, true, true><<<gG, GEMM_T>>>(nullptr, W3);
    k_agg<<<gW, TB>>>(b3);

    // pool + classifier
    k_pool<<<N_GRAPHS, 256>>>(batch);
    k_cls<<<1, 64>>>(Wc1, bc1, Wc2, bc2, out);
}

// round 5
// speedup vs baseline: 1.2527x; 1.2527x over previous
#include <cuda_runtime.h>

#define N_NODES 100000
#define N_EDGES 1600000
#define IN_DIM  128
#define HID     64
#define N_GRAPHS 64

#define SCAN_B 1024
#define SCAN_NB ((N_NODES + SCAN_B - 1) / SCAN_B)   // 98

// ---------------- static device scratch (no allocations allowed) ----------------
__device__ int   g_cnt[N_NODES];          // in-degree (excluding self-loop)
__device__ int   g_cur[N_NODES];          // scatter cursors
__device__ int   g_off[N_NODES + 1];      // CSR offsets by dst
__device__ float g_dis[N_NODES];          // deg^{-1/2}
__device__ int   g_bsum[SCAN_NB];         // per-block sums
__device__ int   g_bpre[SCAN_NB];         // exclusive-scanned block sums
__device__ int   g_csr_src[N_EDGES];
__device__ float g_csr_norm[N_EDGES];
__device__ __align__(16) float g_A[(size_t)N_NODES * HID];  // GEMM output (msg source)
__device__ __align__(16) float g_B[(size_t)N_NODES * HID];  // layer output
__device__ float g_pooled[N_GRAPHS * HID];

// ---------------- preprocessing ----------------
__global__ __launch_bounds__(256) void k_zero() {
    int i = blockIdx.x * blockDim.x + threadIdx.x;
    if (i < N_NODES) { g_cnt[i] = 0; g_cur[i] = 0; }
}

__global__ __launch_bounds__(256) void k_count(const int* __restrict__ dst32) {
    int e = blockIdx.x * blockDim.x + threadIdx.x;
    if (e < N_EDGES) atomicAdd(&g_cnt[dst32[e]], 1);
}

// ---- scan stage 1: coalesced per-block sums, fused with dis = rsqrt(cnt+1) ----
__global__ __launch_bounds__(SCAN_B) void k_scan1() {
    int i = blockIdx.x * SCAN_B + threadIdx.x;
    int v = 0;
    if (i < N_NODES) {
        v = g_cnt[i];
        g_dis[i] = rsqrtf((float)(v + 1));   // +1 self-loop
    }
    int lane = threadIdx.x & 31, wid = threadIdx.x >> 5;
    int s = v;
#pragma unroll
    for (int d = 16; d > 0; d >>= 1) s += __shfl_down_sync(~0u, s, d);
    __shared__ int wsum[32];
    if (lane == 0) wsum[wid] = s;
    __syncthreads();
    if (wid == 0) {
        int t = wsum[lane];
#pragma unroll
        for (int d = 16; d > 0; d >>= 1) t += __shfl_down_sync(~0u, t, d);
        if (lane == 0) g_bsum[blockIdx.x] = t;
    }
}

// ---- scan stage 2: scan the 98 block sums (1 tiny block) ----
__global__ __launch_bounds__(128) void k_scan2() {
    __shared__ int sm[128];
    int t = threadIdx.x;
    int v = (t < SCAN_NB) ? g_bsum[t] : 0;
    sm[t] = v;
    __syncthreads();
    for (int d = 1; d < 128; d <<= 1) {
        int y = (t >= d) ? sm[t - d] : 0;
        __syncthreads();
        sm[t] += y;
        __syncthreads();
    }
    if (t < SCAN_NB) g_bpre[t] = sm[t] - v;     // exclusive
    if (t == 0) g_off[N_NODES] = N_EDGES;
}

// ---- scan stage 3: block-wide exclusive scan + block prefix, coalesced ----
__global__ __launch_bounds__(SCAN_B) void k_scan3() {
    int i = blockIdx.x * SCAN_B + threadIdx.x;
    int v = (i < N_NODES) ? g_cnt[i] : 0;
    int lane = threadIdx.x & 31, wid = threadIdx.x >> 5;
    int x = v;
#pragma unroll
    for (int d = 1; d < 32; d <<= 1) {
        int y = __shfl_up_sync(~0u, x, d);
        if (lane >= d) x += y;
    }
    __shared__ int wsum[32];
    if (lane == 31) wsum[wid] = x;
    __syncthreads();
    if (wid == 0) {
        int s = wsum[lane];
#pragma unroll
        for (int d = 1; d < 32; d <<= 1) {
            int y = __shfl_up_sync(~0u, s, d);
            if (lane >= d) s += y;
        }
        wsum[lane] = s;
    }
    __syncthreads();
    if (i < N_NODES)
        g_off[i] = (x - v) + (wid > 0 ? wsum[wid - 1] : 0) + g_bpre[blockIdx.x];
}

__global__ __launch_bounds__(256) void k_scatter(const int* __restrict__ ei) {
    int e = blockIdx.x * blockDim.x + threadIdx.x;
    if (e >= N_EDGES) return;
    int s = ei[e];
    int d = ei[N_EDGES + e];
    int pos = g_off[d] + atomicAdd(&g_cur[d], 1);
    g_csr_src[pos] = s;
    g_csr_norm[pos] = g_dis[s] * g_dis[d];
}

// ---------------- GEMM: A = act(X) @ W  (X external or g_B) ----------------
#define GEMM_T 128
template<int K, bool RELU, bool FROM_B>
__global__ __launch_bounds__(GEMM_T) void k_gemm(const float* __restrict__ Xext,
                                                 const float* __restrict__ W) {
    __shared__ float Wsh[K * HID];
    for (int i = threadIdx.x; i < K * HID; i += blockDim.x) Wsh[i] = W[i];
    __syncthreads();

    int row = blockIdx.x * blockDim.x + threadIdx.x;
    if (row >= N_NODES) return;

    const float* X = FROM_B ? g_B : Xext;
    const float4* xr = (const float4*)(X + (size_t)row * K);

    float acc[HID];
#pragma unroll
    for (int c = 0; c < HID; c++) acc[c] = 0.0f;

#pragma unroll 2
    for (int k4 = 0; k4 < K / 4; k4++) {
        float4 xv = xr[k4];
        if (RELU) {
            xv.x = fmaxf(xv.x, 0.0f); xv.y = fmaxf(xv.y, 0.0f);
            xv.z = fmaxf(xv.z, 0.0f); xv.w = fmaxf(xv.w, 0.0f);
        }
        float xk_arr[4] = {xv.x, xv.y, xv.z, xv.w};
#pragma unroll
        for (int kk = 0; kk < 4; kk++) {
            float xk = xk_arr[kk];
            const float4* wr = (const float4*)(Wsh + (k4 * 4 + kk) * HID);
#pragma unroll
            for (int c4 = 0; c4 < 16; c4++) {
                float4 w = wr[c4];
                acc[4 * c4 + 0] += xk * w.x;
                acc[4 * c4 + 1] += xk * w.y;
                acc[4 * c4 + 2] += xk * w.z;
                acc[4 * c4 + 3] += xk * w.w;
            }
        }
    }

    float4* o = (float4*)(g_A + (size_t)row * HID);
#pragma unroll
    for (int c4 = 0; c4 < 16; c4++)
        o[c4] = make_float4(acc[4 * c4], acc[4 * c4 + 1], acc[4 * c4 + 2], acc[4 * c4 + 3]);
}

// ---------------- aggregation: one warp per dst node ----------------
// B[d,:] = A[d,:]*dis[d]^2 + b + sum_{e in CSR[d]} A[src_e,:]*norm_e
__global__ __launch_bounds__(256) void k_agg(const float* __restrict__ bias) {
    int w = (blockIdx.x * blockDim.x + threadIdx.x) >> 5;
    if (w >= N_NODES) return;
    int lane = threadIdx.x & 31;

    const float2* A2 = (const float2*)g_A;
    float dis = g_dis[w];
    float2 b2 = ((const float2*)bias)[lane];
    float2 self = A2[(size_t)w * 32 + lane];
    float sn = dis * dis;
    float ax = self.x * sn + b2.x;
    float ay = self.y * sn + b2.y;

    int p   = g_off[w];
    int end = g_off[w + 1];
    for (; p + 2 <= end; p += 2) {
        int   s0 = g_csr_src[p];
        float n0 = g_csr_norm[p];
        int   s1 = g_csr_src[p + 1];
        float n1 = g_csr_norm[p + 1];
        float2 v0 = A2[(size_t)s0 * 32 + lane];
        float2 v1 = A2[(size_t)s1 * 32 + lane];
        ax += v0.x * n0; ay += v0.y * n0;
        ax += v1.x * n1; ay += v1.y * n1;
    }
    if (p < end) {
        int   s0 = g_csr_src[p];
        float n0 = g_csr_norm[p];
        float2 v0 = A2[(size_t)s0 * 32 + lane];
        ax += v0.x * n0; ay += v0.y * n0;
    }

    ((float2*)g_B)[(size_t)w * 32 + lane] = make_float2(ax, ay);
}

// ---------------- global mean pool (batch is sorted int32) ----------------
__device__ __forceinline__ int lb_i32(const int* a, int n, int v) {
    int lo = 0, hi = n;
    while (lo < hi) {
        int mid = (lo + hi) >> 1;
        if (a[mid] < v) lo = mid + 1; else hi = mid;
    }
    return lo;
}

__global__ __launch_bounds__(256) void k_pool(const int* __restrict__ batch) {
    int g = blockIdx.x;                 // one block per graph
    int lo = lb_i32(batch, N_NODES, g);
    int hi = lb_i32(batch, N_NODES, g + 1);
    int c = threadIdx.x & 63;
    int sub = threadIdx.x >> 6;         // 0..3
    float s = 0.0f;
    for (int i = lo + sub; i < hi; i += 4)
        s += g_B[(size_t)i * HID + c];
    __shared__ float red[256];
    red[threadIdx.x] = s;
    __syncthreads();
    if (sub == 0) {
        float tot = red[c] + red[64 + c] + red[128 + c] + red[192 + c];
        float cnt = (float)(hi - lo);
        g_pooled[g * HID + c] = tot / fmaxf(cnt, 1.0f);
    }
}

// ---------------- classifier MLP: [64,64] -> relu[64,32] -> [64,2] ----------------
__global__ __launch_bounds__(64) void k_cls(const float* __restrict__ Wc1,
                                            const float* __restrict__ bc1,
                                            const float* __restrict__ Wc2,
                                            const float* __restrict__ bc2,
                                            float* __restrict__ out) {
    __shared__ float W1s[64 * 32];
    __shared__ float W2s[32 * 2];
    int t = threadIdx.x;  // 64 threads, one per graph
    for (int i = t; i < 64 * 32; i += 64) W1s[i] = Wc1[i];
    if (t < 64) W2s[t] = Wc2[t];
    __syncthreads();

    float p[64];
#pragma unroll
    for (int k = 0; k < 64; k++) p[k] = g_pooled[t * 64 + k];

    float h[32];
#pragma unroll
    for (int j = 0; j < 32; j++) {
        float s = bc1[j];
#pragma unroll
        for (int k = 0; k < 64; k++) s += p[k] * W1s[k * 32 + j];
        h[j] = fmaxf(s, 0.0f);
    }
#pragma unroll
    for (int o = 0; o < 2; o++) {
        float s = bc2[o];
#pragma unroll
        for (int j = 0; j < 32; j++) s += h[j] * W2s[j * 2 + o];
        out[t * 2 + o] = s;
    }
}

// ---------------- launch ----------------
extern "C" void kernel_launch(void* const* d_in, const int* in_sizes, int n_in,
                              void* d_out, int out_size) {
    const float* x     = (const float*)d_in[0];
    const int*   ei    = (const int*)d_in[1];    // int32 (JAX x64 disabled)
    const int*   batch = (const int*)d_in[2];    // int32
    const float* W1  = (const float*)d_in[3];
    const float* b1  = (const float*)d_in[4];
    const float* W2  = (const float*)d_in[5];
    const float* b2  = (const float*)d_in[6];
    const float* W3  = (const float*)d_in[7];
    const float* b3  = (const float*)d_in[8];
    const float* Wc1 = (const float*)d_in[9];
    const float* bc1 = (const float*)d_in[10];
    const float* Wc2 = (const float*)d_in[11];
    const float* bc2 = (const float*)d_in[12];
    float* out = (float*)d_out;

    const int TB = 256;
    const int gN  = (N_NODES + TB - 1) / TB;
    const int gE  = (N_EDGES + TB - 1) / TB;
    const int gW  = (N_NODES * 32 + TB - 1) / TB;        // warp-per-node grid
    const int gG  = (N_NODES + GEMM_T - 1) / GEMM_T;     // gemm grid (128 thr)

    // CSR-by-dst preprocessing
    k_zero<<<gN, TB>>>();
    k_count<<<gE, TB>>>(ei + N_EDGES);
    k_scan1<<<SCAN_NB, SCAN_B>>>();     // block sums + dis
    k_scan2<<<1, 128>>>();              // scan block sums
    k_scan3<<<SCAN_NB, SCAN_B>>>();     // final offsets
    k_scatter<<<gE, TB>>>(ei);

    // layer 1
    k_gemm<IN_DIM, false, false><<<gG, GEMM_T>>>(x, W1);
    k_agg<<<gW, TB>>>(b1);
    // layer 2
    k_gemm<HID, true, true><<<gG, GEMM_T>>>(nullptr, W2);
    k_agg<<<gW, TB>>>(b2);
    // layer 3
    k_gemm<HID, true, true><<<gG, GEMM_T>>>(nullptr, W3);
    k_agg<<<gW, TB>>>(b3);

    // pool + classifier
    k_pool<<<N_GRAPHS, 256>>>(batch);
    k_cls<<<1, 64>>>(Wc1, bc1, Wc2, bc2, out);
}